// round 13
// baseline (speedup 1.0000x reference)
#include <cuda_runtime.h>

// WENO-Z 1-D periodic, B=16 x N=2^20 fp32.
// R12 math (stride-4 lane packing, f2fma diffs, x10-scaled weights) plus:
//  - scalar tail load replaced by one __shfl_down (lane 31 predicated load)
//  - TPB=256 (half the CTAs -> fewer concurrent front-batched LDG bursts).

#define N_ELEMS   1048576
#define N_MASK    (N_ELEMS - 1)
#define TPB       256
#define VEC       8
#define TILE      (TPB * VEC)    // 2048

#define EPS 1e-13f

typedef unsigned long long u64;

__device__ __forceinline__ u64 pk(float lo, float hi) {
    u64 r; asm("mov.b64 %0, {%1, %2};" : "=l"(r) : "f"(lo), "f"(hi)); return r;
}
__device__ __forceinline__ void upk(float& lo, float& hi, u64 v) {
    asm("mov.b64 {%0, %1}, %2;" : "=f"(lo), "=f"(hi) : "l"(v));
}
__device__ __forceinline__ u64 f2mul(u64 a, u64 b) {
    u64 d; asm("mul.rn.f32x2 %0, %1, %2;" : "=l"(d) : "l"(a), "l"(b)); return d;
}
__device__ __forceinline__ u64 f2add(u64 a, u64 b) {
    u64 d; asm("add.rn.f32x2 %0, %1, %2;" : "=l"(d) : "l"(a), "l"(b)); return d;
}
__device__ __forceinline__ u64 f2fma(u64 a, u64 b, u64 c) {
    u64 d; asm("fma.rn.f32x2 %0, %1, %2, %3;" : "=l"(d) : "l"(a), "l"(b), "l"(c)); return d;
}
__device__ __forceinline__ u64 f2abs(u64 a) { return a & 0x7FFFFFFF7FFFFFFFULL; }

__global__ void __launch_bounds__(TPB) weno_z_kernel(
    const float* __restrict__ x, float* __restrict__ out)
{
    const int b     = blockIdx.y;
    const int start = blockIdx.x * TILE;
    const float* xb = x + (size_t)b * N_ELEMS;
    const int t     = threadIdx.x;
    const int lane  = t & 31;

    const int n0 = start + t * VEC;      // first output index for this thread
    // p[k] = x[(n0 - 4 + k) & MASK], k = 0..12 ; outputs at p-index m = 4..11
    const int base = n0 - 4;             // multiple of 4 -> 16B-aligned bases
    float4 f0  = *reinterpret_cast<const float4*>(xb + ((base)      & N_MASK));
    float4 f1  = *reinterpret_cast<const float4*>(xb + ((base + 4)  & N_MASK));
    float4 f2v = *reinterpret_cast<const float4*>(xb + ((base + 8)  & N_MASK));

    // p12 = x[n0+8] = next lane's f1.x (its base = n0+4, f1 = x[n0+8..n0+11]).
    float p12 = __shfl_down_sync(0xFFFFFFFFu, f1.x, 1);
    if (lane == 31) p12 = xb[(base + 12) & N_MASK];

    float p[13];
    p[0]=f0.x;  p[1]=f0.y;  p[2]=f0.z;  p[3]=f0.w;
    p[4]=f1.x;  p[5]=f1.y;  p[6]=f1.z;  p[7]=f1.w;
    p[8]=f2v.x; p[9]=f2v.y; p[10]=f2v.z; p[11]=f2v.w;
    p[12]=p12;

    const u64 Cm1  = pk(-1.0f, -1.0f);
    const u64 C2   = pk(2.0f, 2.0f);
    const u64 C3   = pk(3.0f, 3.0f);
    const u64 C6   = pk(6.0f, 6.0f);
    const u64 C43  = pk(4.0f/3.0f, 4.0f/3.0f);
    const u64 C05  = pk(0.5f, 0.5f);
    const u64 Cm05 = pk(-0.5f, -0.5f);
    const u64 C13  = pk(1.0f/3.0f, 1.0f/3.0f);
    const u64 Cm16 = pk(-1.0f/6.0f, -1.0f/6.0f);
    const u64 Ceps = pk(EPS, EPS);

    // PK[i]  = (p[i],  p[i+4]),  i = 1..8
    // PD1[i] = (d1[i], d1[i+4]), i = 2..8   d1[k] = p[k]-p[k-1]
    // PD2[i] = (d2[i], d2[i+4]), i = 2..7   d2[k] = d1[k+1]-d1[k]
    // R[i]   = d1^2 + 4/3 d2^2 + eps ; c[i] = d1*d2 ; S[i] = R + 2 d2^2 (i=2..5)
    u64 PK[9], PD1[9], PD2[8], R[8], c[8], S[6];

    #pragma unroll
    for (int i = 1; i <= 8; i++) PK[i] = pk(p[i], p[i + 4]);

    #pragma unroll
    for (int i = 2; i <= 8; i++) PD1[i] = f2fma(PK[i - 1], Cm1, PK[i]);

    #pragma unroll
    for (int i = 2; i <= 7; i++) {
        PD2[i] = f2fma(PD1[i], Cm1, PD1[i + 1]);
        u64 sq = f2mul(PD2[i], PD2[i]);
        R[i] = f2fma(PD1[i], PD1[i], f2fma(sq, C43, Ceps));
        c[i] = f2mul(PD1[i], PD2[i]);
        if (i <= 5) S[i] = f2fma(sq, C2, R[i]);
    }

    float o[VEC];

    #pragma unroll
    for (int q = 0; q < 4; q++) {
        const int k0 = q + 2, k1 = q + 3, k2 = q + 4;
        // lanes: output m = 4+q (lane0), m+4 = 8+q (lane1) — all operands aligned

        const u64 IS0 = f2fma(c[k0], C3, S[k0]);
        const u64 IS1 = f2add(R[k1], c[k1]);
        const u64 IS2 = f2fma(c[k2], Cm1, R[k2]);

        const u64 T5 = f2abs(f2fma(IS0, Cm1, IS2));

        // weights scaled x10: d = (1, 6, 3)
        const u64 T6  = f2mul(T5, C6);
        const u64 T3  = f2mul(T5, C3);
        const u64 u0  = f2add(IS0, T5);
        const u64 su1 = f2fma(IS1, C6, T6);
        const u64 su2 = f2fma(IS2, C3, T3);

        const u64 e01 = f2mul(IS0, IS1);
        const u64 e02 = f2mul(IS0, IS2);
        const u64 e12 = f2mul(IS1, IS2);
        const u64 w0 = f2mul(u0,  e12);
        const u64 w1 = f2mul(su1, e02);
        const u64 w2 = f2mul(su2, e01);

        // G = x2 + d1[m-1]/2 ; P0 = G + d2[m-2]/3 ; P1 = G + d2[m-1]/3
        // P2 = x3 - d1[m]/2 - d2[m]/6
        const u64 G  = f2fma(PD1[k1], C05, PK[k1]);
        const u64 P0 = f2fma(PD2[k0], C13, G);
        const u64 P1 = f2fma(PD2[k1], C13, G);
        const u64 P2 = f2fma(PD2[k2], Cm16, f2fma(PD1[k2], Cm05, PK[k2]));

        const u64 num = f2fma(w2, P2, f2fma(w1, P1, f2mul(w0, P0)));
        const u64 den = f2add(f2add(w0, w1), w2);

        float nlo, nhi, dlo, dhi;
        upk(nlo, nhi, num); upk(dlo, dhi, den);
        o[q]     = __fdividef(nlo, dlo);   // output m   = 4+q
        o[q + 4] = __fdividef(nhi, dhi);   // output m+4 = 8+q
    }

    float* ob = out + (size_t)b * N_ELEMS + n0;
    *reinterpret_cast<float4*>(ob)     = make_float4(o[0], o[1], o[2], o[3]);
    *reinterpret_cast<float4*>(ob + 4) = make_float4(o[4], o[5], o[6], o[7]);
}

extern "C" void kernel_launch(void* const* d_in, const int* in_sizes, int n_in,
                              void* d_out, int out_size)
{
    const float* x = (const float*)d_in[0];
    float* out = (float*)d_out;
    const int total = in_sizes[0];
    const int batches = total / N_ELEMS;

    dim3 grid(N_ELEMS / TILE, batches);
    weno_z_kernel<<<grid, TPB>>>(x, out);
}

// round 14
// speedup vs baseline: 1.0654x; 1.0654x over previous
#include <cuda_runtime.h>

// WENO-Z 1-D periodic, B=16 x N=2^20 fp32.
// R12 math (stride-4 lane packing, f2fma diffs, x10-scaled weights),
// TPB=128 (best achieved occupancy), scalar tail via one __shfl_down,
// streaming (.cs) output stores to keep L2 ways for the read stream.

#define N_ELEMS   1048576
#define N_MASK    (N_ELEMS - 1)
#define TPB       128
#define VEC       8
#define TILE      (TPB * VEC)    // 1024

#define EPS 1e-13f

typedef unsigned long long u64;

__device__ __forceinline__ u64 pk(float lo, float hi) {
    u64 r; asm("mov.b64 %0, {%1, %2};" : "=l"(r) : "f"(lo), "f"(hi)); return r;
}
__device__ __forceinline__ void upk(float& lo, float& hi, u64 v) {
    asm("mov.b64 {%0, %1}, %2;" : "=f"(lo), "=f"(hi) : "l"(v));
}
__device__ __forceinline__ u64 f2mul(u64 a, u64 b) {
    u64 d; asm("mul.rn.f32x2 %0, %1, %2;" : "=l"(d) : "l"(a), "l"(b)); return d;
}
__device__ __forceinline__ u64 f2add(u64 a, u64 b) {
    u64 d; asm("add.rn.f32x2 %0, %1, %2;" : "=l"(d) : "l"(a), "l"(b)); return d;
}
__device__ __forceinline__ u64 f2fma(u64 a, u64 b, u64 c) {
    u64 d; asm("fma.rn.f32x2 %0, %1, %2, %3;" : "=l"(d) : "l"(a), "l"(b), "l"(c)); return d;
}
__device__ __forceinline__ u64 f2abs(u64 a) { return a & 0x7FFFFFFF7FFFFFFFULL; }

__device__ __forceinline__ void st_cs_f4(float* p, float a, float b, float c, float d) {
    asm volatile("st.global.cs.v4.f32 [%0], {%1, %2, %3, %4};"
                 :: "l"(p), "f"(a), "f"(b), "f"(c), "f"(d) : "memory");
}

__global__ void __launch_bounds__(TPB) weno_z_kernel(
    const float* __restrict__ x, float* __restrict__ out)
{
    const int b     = blockIdx.y;
    const int start = blockIdx.x * TILE;
    const float* xb = x + (size_t)b * N_ELEMS;
    const int t     = threadIdx.x;
    const int lane  = t & 31;

    const int n0 = start + t * VEC;      // first output index for this thread
    // p[k] = x[(n0 - 4 + k) & MASK], k = 0..12 ; outputs at p-index m = 4..11
    const int base = n0 - 4;             // multiple of 4 -> 16B-aligned bases
    float4 f0  = *reinterpret_cast<const float4*>(xb + ((base)      & N_MASK));
    float4 f1  = *reinterpret_cast<const float4*>(xb + ((base + 4)  & N_MASK));
    float4 f2v = *reinterpret_cast<const float4*>(xb + ((base + 8)  & N_MASK));

    // p12 = x[n0+8] = next lane's f1.x ; lane 31 loads it directly.
    float p12 = __shfl_down_sync(0xFFFFFFFFu, f1.x, 1);
    if (lane == 31) p12 = xb[(base + 12) & N_MASK];

    float p[13];
    p[0]=f0.x;  p[1]=f0.y;  p[2]=f0.z;  p[3]=f0.w;
    p[4]=f1.x;  p[5]=f1.y;  p[6]=f1.z;  p[7]=f1.w;
    p[8]=f2v.x; p[9]=f2v.y; p[10]=f2v.z; p[11]=f2v.w;
    p[12]=p12;

    const u64 Cm1  = pk(-1.0f, -1.0f);
    const u64 C2   = pk(2.0f, 2.0f);
    const u64 C3   = pk(3.0f, 3.0f);
    const u64 C6   = pk(6.0f, 6.0f);
    const u64 C43  = pk(4.0f/3.0f, 4.0f/3.0f);
    const u64 C05  = pk(0.5f, 0.5f);
    const u64 Cm05 = pk(-0.5f, -0.5f);
    const u64 C13  = pk(1.0f/3.0f, 1.0f/3.0f);
    const u64 Cm16 = pk(-1.0f/6.0f, -1.0f/6.0f);
    const u64 Ceps = pk(EPS, EPS);

    // PK[i]  = (p[i],  p[i+4]),  i = 1..8
    // PD1[i] = (d1[i], d1[i+4]), i = 2..8   d1[k] = p[k]-p[k-1]
    // PD2[i] = (d2[i], d2[i+4]), i = 2..7   d2[k] = d1[k+1]-d1[k]
    // R[i]   = d1^2 + 4/3 d2^2 + eps ; c[i] = d1*d2 ; S[i] = R + 2 d2^2 (i=2..5)
    u64 PK[9], PD1[9], PD2[8], R[8], c[8], S[6];

    #pragma unroll
    for (int i = 1; i <= 8; i++) PK[i] = pk(p[i], p[i + 4]);

    #pragma unroll
    for (int i = 2; i <= 8; i++) PD1[i] = f2fma(PK[i - 1], Cm1, PK[i]);

    #pragma unroll
    for (int i = 2; i <= 7; i++) {
        PD2[i] = f2fma(PD1[i], Cm1, PD1[i + 1]);
        u64 sq = f2mul(PD2[i], PD2[i]);
        R[i] = f2fma(PD1[i], PD1[i], f2fma(sq, C43, Ceps));
        c[i] = f2mul(PD1[i], PD2[i]);
        if (i <= 5) S[i] = f2fma(sq, C2, R[i]);
    }

    float o[VEC];

    #pragma unroll
    for (int q = 0; q < 4; q++) {
        const int k0 = q + 2, k1 = q + 3, k2 = q + 4;
        // lanes: output m = 4+q (lane0), m+4 = 8+q (lane1) — all operands aligned

        const u64 IS0 = f2fma(c[k0], C3, S[k0]);
        const u64 IS1 = f2add(R[k1], c[k1]);
        const u64 IS2 = f2fma(c[k2], Cm1, R[k2]);

        const u64 T5 = f2abs(f2fma(IS0, Cm1, IS2));

        // weights scaled x10: d = (1, 6, 3)
        const u64 T6  = f2mul(T5, C6);
        const u64 T3  = f2mul(T5, C3);
        const u64 u0  = f2add(IS0, T5);
        const u64 su1 = f2fma(IS1, C6, T6);
        const u64 su2 = f2fma(IS2, C3, T3);

        const u64 e01 = f2mul(IS0, IS1);
        const u64 e02 = f2mul(IS0, IS2);
        const u64 e12 = f2mul(IS1, IS2);
        const u64 w0 = f2mul(u0,  e12);
        const u64 w1 = f2mul(su1, e02);
        const u64 w2 = f2mul(su2, e01);

        // G = x2 + d1[m-1]/2 ; P0 = G + d2[m-2]/3 ; P1 = G + d2[m-1]/3
        // P2 = x3 - d1[m]/2 - d2[m]/6
        const u64 G  = f2fma(PD1[k1], C05, PK[k1]);
        const u64 P0 = f2fma(PD2[k0], C13, G);
        const u64 P1 = f2fma(PD2[k1], C13, G);
        const u64 P2 = f2fma(PD2[k2], Cm16, f2fma(PD1[k2], Cm05, PK[k2]));

        const u64 num = f2fma(w2, P2, f2fma(w1, P1, f2mul(w0, P0)));
        const u64 den = f2add(f2add(w0, w1), w2);

        float nlo, nhi, dlo, dhi;
        upk(nlo, nhi, num); upk(dlo, dhi, den);
        o[q]     = __fdividef(nlo, dlo);   // output m   = 4+q
        o[q + 4] = __fdividef(nhi, dhi);   // output m+4 = 8+q
    }

    float* ob = out + (size_t)b * N_ELEMS + n0;
    st_cs_f4(ob,     o[0], o[1], o[2], o[3]);
    st_cs_f4(ob + 4, o[4], o[5], o[6], o[7]);
}

extern "C" void kernel_launch(void* const* d_in, const int* in_sizes, int n_in,
                              void* d_out, int out_size)
{
    const float* x = (const float*)d_in[0];
    float* out = (float*)d_out;
    const int total = in_sizes[0];
    const int batches = total / N_ELEMS;

    dim3 grid(N_ELEMS / TILE, batches);
    weno_z_kernel<<<grid, TPB>>>(x, out);
}